// round 11
// baseline (speedup 1.0000x reference)
#include <cuda_runtime.h>
#include <cuda_fp16.h>

// Lag2Eul CIC deposit: x (2,4,128,128,128) f32 -> out (2,1,128,128,128) f32
// DIS_NORM = 6*512/1000 = 3.072
//
// f16x2 packed-atomic scheme: each (d,h)-corner deposits its w-pair
// (cells t2, t2+1) as ONE RED.ADD.F16x2 into one of two staggered meshes:
//   mesh A word k holds cells (2k,   2k+1)   -> even t2
//   mesh B word j holds cells (2j-1, 2j)     -> odd  t2 (j = (t2+1)/2)
// B rows have 65 words; B[0].lo (cell -1) and B[64].hi (cell 128) are dead
// slots that silently absorb out-of-range halves. Convert kernel sums
// A+B into f32 out.

#define PNUM  (128*128*128)      // 2097152
#define NB    2
#define DISN  3.072f
#define RBLK  64                 // partial-sum blocks per (n,dim)
#define SBLK  592                // persistent scatter blocks (8/SM exactly)

#define AW    64                 // A words per w-row
#define BW    65                 // B words per w-row (incl. guard)
#define NROW  (128*128)          // (d,h) rows per batch
#define ASZ   (NROW*AW)          // 1048576 words per batch
#define BSZ   (NROW*BW)          // 1064960 words per batch

__device__ float   g_part[6 * RBLK];
__device__ __half2 g_A[NB * ASZ];
__device__ __half2 g_B[NB * BSZ];

// grid (RBLK, 6), 256 threads. Sums channel chunks into g_part and zeroes
// the f16 scratch meshes (fused under the read bandwidth).
__global__ void __launch_bounds__(256)
reduce_and_zero_kernel(const float* __restrict__ x) {
    int y = blockIdx.y;                 // n*3 + dim
    int n = y / 3, c = y % 3;
    const int CHUNK4 = PNUM / 4 / RBLK;
    const float4* base = (const float4*)(x + ((size_t)n * 4 + c) * PNUM)
                       + (size_t)blockIdx.x * CHUNK4;

    // fused zeroing of both scratch meshes (A: 2M words, B: 2129920 words)
    {
        const int NBLK = RBLK * 6;      // 384 blocks
        int bid = blockIdx.y * RBLK + blockIdx.x;
        uint4* a4 = (uint4*)g_A;
        uint4* b4 = (uint4*)g_B;
        const int A4 = NB * ASZ / 4;    // 524288
        const int B4 = NB * BSZ / 4;    // 532480
        const uint4 z = make_uint4(0u, 0u, 0u, 0u);
        for (int i = bid * 256 + threadIdx.x; i < A4; i += NBLK * 256)
            a4[i] = z;
        for (int i = bid * 256 + threadIdx.x; i < B4; i += NBLK * 256)
            b4[i] = z;
    }

    float s = 0.0f;
    for (int i = threadIdx.x; i < CHUNK4; i += 256) {
        float4 v = base[i];
        s += (v.x + v.y) + (v.z + v.w);
    }
    #pragma unroll
    for (int o = 16; o > 0; o >>= 1)
        s += __shfl_down_sync(0xffffffffu, s, o);

    __shared__ float ws[8];
    if ((threadIdx.x & 31) == 0) ws[threadIdx.x >> 5] = s;
    __syncthreads();
    if (threadIdx.x < 8) {
        s = ws[threadIdx.x];
        #pragma unroll
        for (int o = 4; o > 0; o >>= 1)
            s += __shfl_down_sync(0xffu, s, o);
        if (threadIdx.x == 0) g_part[y * RBLK + blockIdx.x] = s;
    }
}

// Persistent scatter: grid (SBLK, NB), 256 threads, grid-stride over
// particle*4 + corner. 4 lanes/particle (bit0 -> h corner, bit1 -> d corner);
// each lane deposits its w-pair as one f16x2 RED.
__global__ void __launch_bounds__(256)
scatter_kernel(const float* __restrict__ x) {
    int n = blockIdx.y;

    __shared__ float smean[3];
    int wid = threadIdx.x >> 5, lid = threadIdx.x & 31;
    if (wid < 3) {
        float s = g_part[(n * 3 + wid) * RBLK + lid]
                + g_part[(n * 3 + wid) * RBLK + 32 + lid];
        #pragma unroll
        for (int o = 16; o > 0; o >>= 1)
            s += __shfl_down_sync(0xffffffffu, s, o);
        if (lid == 0) smean[wid] = s * (1.0f / (float)PNUM);
    }
    __syncthreads();
    const float m0 = smean[0], m1 = smean[1], m2 = smean[2];

    const float* xb = x + (size_t)n * 4 * PNUM;
    __half2* An = g_A + (size_t)n * ASZ;
    __half2* Bn = g_B + (size_t)n * BSZ;
    const int TOT = PNUM * 4;        // 8388608
    const int STRIDE = SBLK * 256;

    for (int t = blockIdx.x * 256 + threadIdx.x; t < TOT; t += STRIDE) {
        int p = t >> 2;
        int corner = t & 3;

        int w = p & 127;
        int h = (p >> 7) & 127;
        int d = p >> 14;

        // 4 lanes share each address -> warp-broadcast loads.
        float p0 = (__ldg(xb + p)            - m0) * DISN + (float)d + 0.5f;
        float p1 = (__ldg(xb + PNUM + p)     - m1) * DISN + (float)h + 0.5f;
        float p2 = (__ldg(xb + 2 * PNUM + p) - m2) * DISN + (float)w + 0.5f;
        float v  =  __ldg(xb + 3 * PNUM + p);

        float i0 = floorf(p0), i1 = floorf(p1), i2 = floorf(p2);
        float f0 = p0 - i0, f1 = p1 - i1, f2 = p2 - i2;
        int t0 = (int)i0, t1 = (int)i1, t2 = (int)i2;

        int ch = corner & 1;
        int cd = (corner >> 1) & 1;
        int a0 = t0 + cd;
        int a1 = t1 + ch;

        if (((unsigned)a0 < 128u) & ((unsigned)a1 < 128u)) {
            float base = v * (cd ? f0 : 1.0f - f0) * (ch ? f1 : 1.0f - f1);
            __half2 hv = __floats2half2_rn(base * (1.0f - f2), base * f2);
            int row = (a0 << 7) + a1;

            bool odd = (t2 & 1) != 0;
            // even t2: A word t2/2, valid for 0 <= t2 <= 126
            // odd  t2: B word (t2+1)/2, valid for -1 <= t2 <= 127
            //          (dead slots absorb cells -1 and 128)
            __half2* addr;
            bool valid;
            if (odd) {
                valid = (t2 >= -1) & (t2 <= 127);
                addr = Bn + row * BW + ((t2 + 1) >> 1);
            } else {
                valid = ((unsigned)t2 <= 126u);
                addr = An + (row << 6) + (t2 >> 1);
            }
            if (valid) atomicAdd(addr, hv);
        }
    }
}

// Convert: one thread per A-word (2 output cells).
// cell 2k   = A[k].lo + B[k].hi     (B word k holds cells 2k-1, 2k)
// cell 2k+1 = A[k].hi + B[k+1].lo
__global__ void __launch_bounds__(256)
convert_kernel(float* __restrict__ out) {
    int g = blockIdx.x * 256 + threadIdx.x;      // [0, NB*ASZ)
    int n = g >> 20;                             // ASZ = 2^20
    int rem = g & (ASZ - 1);
    int row = rem >> 6;
    int k = rem & 63;

    __half2 a  = g_A[(size_t)n * ASZ + rem];
    const __half2* brow = g_B + (size_t)n * BSZ + row * BW;
    __half2 b0 = brow[k];
    __half2 b1 = brow[k + 1];

    float2 r;
    r.x = __low2float(a)  + __high2float(b0);
    r.y = __high2float(a) + __low2float(b1);
    ((float2*)out)[((size_t)n * PNUM + (row << 7)) / 2 + k] = r;
}

extern "C" void kernel_launch(void* const* d_in, const int* in_sizes, int n_in,
                              void* d_out, int out_size) {
    const float* x = (const float*)d_in[0];
    float* out = (float*)d_out;

    dim3 rgrid(RBLK, 6);
    reduce_and_zero_kernel<<<rgrid, 256>>>(x);

    dim3 sgrid(SBLK, NB);
    scatter_kernel<<<sgrid, 256>>>(x);

    convert_kernel<<<NB * ASZ / 256, 256>>>(out);
}

// round 12
// speedup vs baseline: 1.5086x; 1.5086x over previous
#include <cuda_runtime.h>

// Lag2Eul CIC deposit: x (2,4,128,128,128) f32 -> out (2,1,128,128,128) f32
// DIS_NORM = 6*512/1000 = 3.072

#define PNUM  (128*128*128)      // 2097152
#define NB    2
#define DISN  3.072f
#define RBLK  128                // partial-sum blocks per (n,dim) -> 768 blocks
#define SBLK  592                // persistent scatter blocks per batch (8/SM)

__device__ float g_part[6 * RBLK];   // overwritten every run: no zeroing needed

// grid (RBLK, 6), 256 threads. Each block:
//   - sums a contiguous 1/RBLK chunk of channel (n,c) into g_part
//   - zeroes a slice of the output (fused, rides free under the read BW)
__global__ void __launch_bounds__(256)
reduce_and_zero_kernel(const float* __restrict__ x, float* __restrict__ out) {
    int y = blockIdx.y;                 // n*3 + dim
    int n = y / 3, c = y % 3;
    const int CHUNK4 = PNUM / 4 / RBLK; // float4 elements per block (4096)
    const float4* base = (const float4*)(x + ((size_t)n * 4 + c) * PNUM)
                       + (size_t)blockIdx.x * CHUNK4;

    // fused zeroing of the output: RBLK*6 blocks cover NB*PNUM floats
    {
        const int TOT4 = NB * PNUM / 4;
        const int NBLK = RBLK * 6;      // 768
        int bid = blockIdx.y * RBLK + blockIdx.x;
        float4* o4 = (float4*)out;
        const float4 z = make_float4(0.f, 0.f, 0.f, 0.f);
        for (int i = bid * 256 + threadIdx.x; i < TOT4; i += NBLK * 256)
            o4[i] = z;
    }

    float s = 0.0f;
    #pragma unroll 4
    for (int i = threadIdx.x; i < CHUNK4; i += 256) {
        float4 v = base[i];
        s += (v.x + v.y) + (v.z + v.w);
    }
    #pragma unroll
    for (int o = 16; o > 0; o >>= 1)
        s += __shfl_down_sync(0xffffffffu, s, o);

    __shared__ float ws[8];
    if ((threadIdx.x & 31) == 0) ws[threadIdx.x >> 5] = s;
    __syncthreads();
    if (threadIdx.x < 8) {
        s = ws[threadIdx.x];
        #pragma unroll
        for (int o = 4; o > 0; o >>= 1)
            s += __shfl_down_sync(0xffu, s, o);
        if (threadIdx.x == 0) g_part[y * RBLK + blockIdx.x] = s;
    }
}

// Persistent scatter: grid (SBLK, NB), 256 threads, grid-stride over
// particle*8+corner. 8 lanes per particle, corner bits:
//   bit0 -> w offset (adjacent lanes hit adjacent addresses => sector merge)
//   bit1 -> h offset, bit2 -> d offset
// One warp-wide RED.ADD.F32 covers 4 particles x 8 corners; w-pairs coalesce
// into one 32B-sector wavefront 7/8 of the time. (R7 body — proven fastest.)
__global__ void __launch_bounds__(256)
scatter_kernel(const float* __restrict__ x, float* __restrict__ out) {
    int n = blockIdx.y;

    // Per-block mean finalize: warps 0-2, each lane folds 4 partials.
    __shared__ float smean[3];
    int wid = threadIdx.x >> 5, lid = threadIdx.x & 31;
    if (wid < 3) {
        const float* gp = g_part + (n * 3 + wid) * RBLK;
        float s = gp[lid] + gp[lid + 32] + gp[lid + 64] + gp[lid + 96];
        #pragma unroll
        for (int o = 16; o > 0; o >>= 1)
            s += __shfl_down_sync(0xffffffffu, s, o);
        if (lid == 0) smean[wid] = s * (1.0f / (float)PNUM);
    }
    __syncthreads();
    const float m0 = smean[0], m1 = smean[1], m2 = smean[2];

    const float* xb = x + (size_t)n * 4 * PNUM;
    float* ob = out + (size_t)n * PNUM;
    const int TOT = PNUM * 8;
    const int STRIDE = SBLK * 256;

    for (int t = blockIdx.x * 256 + threadIdx.x; t < TOT; t += STRIDE) {
        int p = t >> 3;
        int corner = t & 7;

        int w = p & 127;
        int h = (p >> 7) & 127;
        int d = p >> 14;

        // 8 lanes share each address -> warp-broadcast loads.
        float p0 = (__ldg(xb + p)            - m0) * DISN + (float)d + 0.5f;
        float p1 = (__ldg(xb + PNUM + p)     - m1) * DISN + (float)h + 0.5f;
        float p2 = (__ldg(xb + 2 * PNUM + p) - m2) * DISN + (float)w + 0.5f;
        float v  =  __ldg(xb + 3 * PNUM + p);

        float i0 = floorf(p0), i1 = floorf(p1), i2 = floorf(p2);
        float f0 = p0 - i0, f1 = p1 - i1, f2 = p2 - i2;
        int t0 = (int)i0, t1 = (int)i1, t2 = (int)i2;

        int cw = corner & 1;
        int ch = (corner >> 1) & 1;
        int cd = (corner >> 2) & 1;

        int a0 = t0 + cd;
        int a1 = t1 + ch;
        int a2 = t2 + cw;

        float wt = (cd ? f0 : 1.0f - f0)
                 * (ch ? f1 : 1.0f - f1)
                 * (cw ? f2 : 1.0f - f2);

        if (((unsigned)a0 < 128u) & ((unsigned)a1 < 128u) &
            ((unsigned)a2 < 128u))
            atomicAdd(&ob[(a0 << 14) + (a1 << 7) + a2], v * wt);
    }
}

extern "C" void kernel_launch(void* const* d_in, const int* in_sizes, int n_in,
                              void* d_out, int out_size) {
    const float* x = (const float*)d_in[0];
    float* out = (float*)d_out;

    dim3 rgrid(RBLK, 6);
    reduce_and_zero_kernel<<<rgrid, 256>>>(x, out);

    dim3 sgrid(SBLK, NB);
    scatter_kernel<<<sgrid, 256>>>(x, out);
}